// round 3
// baseline (speedup 1.0000x reference)
#include <cuda_runtime.h>
#include <cstdint>

#define BATCH 4
#define SEQ   2048
#define DIN   1024
#define DQ    1024
#define DV    1024

// Scratch (allocation-free rule: __device__ globals)
__device__ float g_q[(size_t)BATCH * SEQ * DQ];
__device__ float g_k[(size_t)BATCH * SEQ * DQ];
__device__ float g_v[(size_t)BATCH * SEQ * DV];
__device__ float g_p[(size_t)BATCH * SEQ * SEQ];

__device__ __forceinline__ uint32_t f2tf32(float x) {
    uint32_t r;
    asm("cvt.rna.tf32.f32 %0, %1;" : "=r"(r) : "f"(x));
    return r;
}

__device__ __forceinline__ void mma8(float* c, const uint32_t* a, const uint32_t* b) {
    asm volatile(
        "mma.sync.aligned.m16n8k8.row.col.f32.tf32.tf32.f32 "
        "{%0,%1,%2,%3}, {%4,%5,%6,%7}, {%8,%9}, {%0,%1,%2,%3};"
        : "+f"(c[0]), "+f"(c[1]), "+f"(c[2]), "+f"(c[3])
        : "r"(a[0]), "r"(a[1]), "r"(a[2]), "r"(a[3]), "r"(b[0]), "r"(b[1]));
}

__device__ __forceinline__ void cpa16(float* s, const float* g) {
    unsigned sa = (unsigned)__cvta_generic_to_shared(s);
    asm volatile("cp.async.cg.shared.global [%0], [%1], 16;" :: "r"(sa), "l"(g));
}
__device__ __forceinline__ void cpa_commit() { asm volatile("cp.async.commit_group;"); }
__device__ __forceinline__ void cpa_wait0()  { asm volatile("cp.async.wait_group 0;"); }
__device__ __forceinline__ void cpa_wait1()  { asm volatile("cp.async.wait_group 1;"); }

// ---------------------------------------------------------------------------
// GEMM NT: C[m][n] = sum_k A[m][k] * B[n][k]  (+ epilogue)
//   epi 0: C += bias[n]        (projections)
//   epi 1: C = mask ? -1e9 : C*scale   (attention scores; mask is int32 0/1)
// Tiles: BM=BN=128, BK=32. 256 threads, 8 warps (2x4), warp tile 64x32.
// Smem rows padded to 36 floats -> conflict-free fragment LDS.
// ---------------------------------------------------------------------------
__global__ __launch_bounds__(256, 2)
void gemm_nt_kernel(const float* __restrict__ A, long sAz,
                    const float* __restrict__ B, long sBz,
                    const float* __restrict__ bias,
                    const int* __restrict__ mask, long sMz,
                    float* __restrict__ C, long sCz,
                    int N, int K, float scale, int epi)
{
    extern __shared__ float sm[];
    float* sA = sm;              // [2][128][36]
    float* sB = sm + 2 * 128 * 36;

    const int tid  = threadIdx.x;
    const int lane = tid & 31, warp = tid >> 5;
    const int wm = warp >> 2, wn = warp & 3;   // 2 x 4 warp grid
    const int gq = lane >> 2, tg = lane & 3;

    const float* Ab = A + (long)blockIdx.z * sAz + (long)blockIdx.y * 128 * K;
    const float* Bb = B + (long)blockIdx.z * sBz + (long)blockIdx.x * 128 * K;

    float acc[4][4][4];
#pragma unroll
    for (int i = 0; i < 4; i++)
#pragma unroll
        for (int j = 0; j < 4; j++)
#pragma unroll
            for (int l = 0; l < 4; l++) acc[i][j][l] = 0.f;

    const int NIT = K >> 5;

    // prologue: stage 0
#pragma unroll
    for (int i = 0; i < 4; i++) {
        int idx = i * 256 + tid;
        int r = idx >> 3, c = (idx & 7) << 2;
        cpa16(&sA[r * 36 + c], Ab + (long)r * K + c);
        cpa16(&sB[r * 36 + c], Bb + (long)r * K + c);
    }
    cpa_commit();

    for (int it = 0; it < NIT; ++it) {
        int s = it & 1;
        if (it + 1 < NIT) {
            int k0 = (it + 1) << 5;
            float* dA = sA + (s ^ 1) * 4608;
            float* dB = sB + (s ^ 1) * 4608;
#pragma unroll
            for (int i = 0; i < 4; i++) {
                int idx = i * 256 + tid;
                int r = idx >> 3, c = (idx & 7) << 2;
                cpa16(&dA[r * 36 + c], Ab + (long)r * K + k0 + c);
                cpa16(&dB[r * 36 + c], Bb + (long)r * K + k0 + c);
            }
            cpa_commit();
            cpa_wait1();
        } else {
            cpa_wait0();
        }
        __syncthreads();

        const float* cA = sA + s * 4608;
        const float* cB = sB + s * 4608;
#pragma unroll
        for (int ks = 0; ks < 4; ++ks) {
            uint32_t af[4][4];
            uint32_t bf[4][2];
#pragma unroll
            for (int mt = 0; mt < 4; ++mt) {
                int r = wm * 64 + mt * 16 + gq;
                int c = ks * 8 + tg;
                af[mt][0] = f2tf32(cA[r * 36 + c]);
                af[mt][1] = f2tf32(cA[(r + 8) * 36 + c]);
                af[mt][2] = f2tf32(cA[r * 36 + c + 4]);
                af[mt][3] = f2tf32(cA[(r + 8) * 36 + c + 4]);
            }
#pragma unroll
            for (int nt = 0; nt < 4; ++nt) {
                int r = wn * 32 + nt * 8 + gq;
                int c = ks * 8 + tg;
                bf[nt][0] = f2tf32(cB[r * 36 + c]);
                bf[nt][1] = f2tf32(cB[r * 36 + c + 4]);
            }
#pragma unroll
            for (int mt = 0; mt < 4; ++mt)
#pragma unroll
                for (int nt = 0; nt < 4; ++nt)
                    mma8(acc[mt][nt], af[mt], bf[nt]);
        }
        __syncthreads();
    }

    // epilogue
    C += (long)blockIdx.z * sCz;
    if (epi == 1) mask += (long)blockIdx.z * sMz;
#pragma unroll
    for (int mt = 0; mt < 4; ++mt) {
        int row = blockIdx.y * 128 + wm * 64 + mt * 16 + gq;
#pragma unroll
        for (int nt = 0; nt < 4; ++nt) {
            int col = blockIdx.x * 128 + wn * 32 + nt * 8 + tg * 2;
            float* a = acc[mt][nt];
            long r0 = (long)row * N, r1 = (long)(row + 8) * N;
            if (epi == 0) {
                float b0 = bias[col], b1 = bias[col + 1];
                C[r0 + col]     = a[0] + b0;
                C[r0 + col + 1] = a[1] + b1;
                C[r1 + col]     = a[2] + b0;
                C[r1 + col + 1] = a[3] + b1;
            } else {
                C[r0 + col]     = mask[r0 + col]     ? -1.0e9f : a[0] * scale;
                C[r0 + col + 1] = mask[r0 + col + 1] ? -1.0e9f : a[1] * scale;
                C[r1 + col]     = mask[r1 + col]     ? -1.0e9f : a[2] * scale;
                C[r1 + col + 1] = mask[r1 + col + 1] ? -1.0e9f : a[3] * scale;
            }
        }
    }
}

// ---------------------------------------------------------------------------
// GEMM NN: C[m][n] = sum_k A[m][k] * B[k][n]   (out = P @ V)
// B smem tile stored [BK=32][BN+4=132] -> conflict-free fragment LDS.
// ---------------------------------------------------------------------------
__global__ __launch_bounds__(256, 2)
void gemm_nn_kernel(const float* __restrict__ A, long sAz,
                    const float* __restrict__ B, long sBz,
                    float* __restrict__ C, long sCz,
                    int N, int K)
{
    extern __shared__ float sm[];
    float* sA = sm;            // [2][128][36] = 9216 floats
    float* sB = sm + 9216;     // [2][32][132] = 8448 floats

    const int tid  = threadIdx.x;
    const int lane = tid & 31, warp = tid >> 5;
    const int wm = warp >> 2, wn = warp & 3;
    const int gq = lane >> 2, tg = lane & 3;

    const float* Ab = A + (long)blockIdx.z * sAz + (long)blockIdx.y * 128 * K;
    const float* Bb = B + (long)blockIdx.z * sBz + (long)blockIdx.x * 128;

    float acc[4][4][4];
#pragma unroll
    for (int i = 0; i < 4; i++)
#pragma unroll
        for (int j = 0; j < 4; j++)
#pragma unroll
            for (int l = 0; l < 4; l++) acc[i][j][l] = 0.f;

    const int NIT = K >> 5;

#pragma unroll
    for (int i = 0; i < 4; i++) {
        int idx = i * 256 + tid;
        int ra = idx >> 3, ca = (idx & 7) << 2;
        cpa16(&sA[ra * 36 + ca], Ab + (long)ra * K + ca);
        int rb = idx >> 5, cb = (idx & 31) << 2;
        cpa16(&sB[rb * 132 + cb], Bb + (long)rb * N + cb);
    }
    cpa_commit();

    for (int it = 0; it < NIT; ++it) {
        int s = it & 1;
        if (it + 1 < NIT) {
            int k0 = (it + 1) << 5;
            float* dA = sA + (s ^ 1) * 4608;
            float* dB = sB + (s ^ 1) * 4224;
#pragma unroll
            for (int i = 0; i < 4; i++) {
                int idx = i * 256 + tid;
                int ra = idx >> 3, ca = (idx & 7) << 2;
                cpa16(&dA[ra * 36 + ca], Ab + (long)ra * K + k0 + ca);
                int rb = idx >> 5, cb = (idx & 31) << 2;
                cpa16(&dB[rb * 132 + cb], Bb + (long)(k0 + rb) * N + cb);
            }
            cpa_commit();
            cpa_wait1();
        } else {
            cpa_wait0();
        }
        __syncthreads();

        const float* cA = sA + s * 4608;
        const float* cB = sB + s * 4224;
#pragma unroll
        for (int ks = 0; ks < 4; ++ks) {
            uint32_t af[4][4];
            uint32_t bf[4][2];
#pragma unroll
            for (int mt = 0; mt < 4; ++mt) {
                int r = wm * 64 + mt * 16 + gq;
                int c = ks * 8 + tg;
                af[mt][0] = f2tf32(cA[r * 36 + c]);
                af[mt][1] = f2tf32(cA[(r + 8) * 36 + c]);
                af[mt][2] = f2tf32(cA[r * 36 + c + 4]);
                af[mt][3] = f2tf32(cA[(r + 8) * 36 + c + 4]);
            }
#pragma unroll
            for (int nt = 0; nt < 4; ++nt) {
                int n = wn * 32 + nt * 8 + gq;
                int k = ks * 8 + tg;
                bf[nt][0] = f2tf32(cB[k * 132 + n]);
                bf[nt][1] = f2tf32(cB[(k + 4) * 132 + n]);
            }
#pragma unroll
            for (int mt = 0; mt < 4; ++mt)
#pragma unroll
                for (int nt = 0; nt < 4; ++nt)
                    mma8(acc[mt][nt], af[mt], bf[nt]);
        }
        __syncthreads();
    }

    C += (long)blockIdx.z * sCz;
#pragma unroll
    for (int mt = 0; mt < 4; ++mt) {
        int row = blockIdx.y * 128 + wm * 64 + mt * 16 + gq;
#pragma unroll
        for (int nt = 0; nt < 4; ++nt) {
            int col = blockIdx.x * 128 + wn * 32 + nt * 8 + tg * 2;
            float* a = acc[mt][nt];
            long r0 = (long)row * N, r1 = (long)(row + 8) * N;
            C[r0 + col]     = a[0];
            C[r0 + col + 1] = a[1];
            C[r1 + col]     = a[2];
            C[r1 + col + 1] = a[3];
        }
    }
}

// ---------------------------------------------------------------------------
// Row softmax over P: one block per row (SEQ=2048 elems, 256 threads x 8).
// ---------------------------------------------------------------------------
__global__ void softmax_kernel(float* __restrict__ P)
{
    float* p = P + (long)blockIdx.x * SEQ;
    const int tid = threadIdx.x;
    __shared__ float red[8];

    float v[8];
    float mx = -3.4e38f;
#pragma unroll
    for (int i = 0; i < 8; i++) {
        v[i] = p[tid + (i << 8)];
        mx = fmaxf(mx, v[i]);
    }
#pragma unroll
    for (int o = 16; o > 0; o >>= 1) mx = fmaxf(mx, __shfl_xor_sync(0xffffffffu, mx, o));
    if ((tid & 31) == 0) red[tid >> 5] = mx;
    __syncthreads();
    mx = red[0];
#pragma unroll
    for (int i = 1; i < 8; i++) mx = fmaxf(mx, red[i]);

    float sum = 0.f;
#pragma unroll
    for (int i = 0; i < 8; i++) {
        v[i] = expf(v[i] - mx);
        sum += v[i];
    }
#pragma unroll
    for (int o = 16; o > 0; o >>= 1) sum += __shfl_xor_sync(0xffffffffu, sum, o);
    __syncthreads();
    if ((tid & 31) == 0) red[tid >> 5] = sum;
    __syncthreads();
    float tot = 0.f;
#pragma unroll
    for (int i = 0; i < 8; i++) tot += red[i];
    float inv = 1.0f / tot;
#pragma unroll
    for (int i = 0; i < 8; i++) p[tid + (i << 8)] = v[i] * inv;
}

// ---------------------------------------------------------------------------
extern "C" void kernel_launch(void* const* d_in, const int* in_sizes, int n_in,
                              void* d_out, int out_size)
{
    const float* query = (const float*)d_in[0];
    const float* key   = (const float*)d_in[1];
    const float* value = (const float*)d_in[2];
    const int*   mask  = (const int*)d_in[3];     // bool stored as int32
    const float* Wq = (const float*)d_in[4];
    const float* bq = (const float*)d_in[5];
    const float* Wk = (const float*)d_in[6];
    const float* bk = (const float*)d_in[7];
    const float* Wv = (const float*)d_in[8];
    const float* bv = (const float*)d_in[9];
    float* out = (float*)d_out;

    float *qb, *kb, *vb, *pb;
    cudaGetSymbolAddress((void**)&qb, g_q);
    cudaGetSymbolAddress((void**)&kb, g_k);
    cudaGetSymbolAddress((void**)&vb, g_v);
    cudaGetSymbolAddress((void**)&pb, g_p);

    const int SMEM_NT = (2 * 128 * 36 * 2) * 4;              // 73728 B
    const int SMEM_NN = (2 * 128 * 36 + 2 * 32 * 132) * 4;   // 70656 B
    cudaFuncSetAttribute(gemm_nt_kernel, cudaFuncAttributeMaxDynamicSharedMemorySize, SMEM_NT);
    cudaFuncSetAttribute(gemm_nn_kernel, cudaFuncAttributeMaxDynamicSharedMemorySize, SMEM_NN);

    dim3 blk(256);

    // QKV projections: M = B*S = 8192, N = 1024, K = 1024
    dim3 gp(DQ / 128, (BATCH * SEQ) / 128, 1);
    gemm_nt_kernel<<<gp, blk, SMEM_NT>>>(query, 0, Wq, 0, bq, nullptr, 0, qb, 0, DQ, DIN, 0.f, 0);
    gemm_nt_kernel<<<gp, blk, SMEM_NT>>>(key,   0, Wk, 0, bk, nullptr, 0, kb, 0, DQ, DIN, 0.f, 0);
    gemm_nt_kernel<<<gp, blk, SMEM_NT>>>(value, 0, Wv, 0, bv, nullptr, 0, vb, 0, DV, DIN, 0.f, 0);

    // scores: per batch M = N = SEQ, K = DQ, scale = 1/sqrt(1024)
    dim3 gs(SEQ / 128, SEQ / 128, BATCH);
    gemm_nt_kernel<<<gs, blk, SMEM_NT>>>(qb, (long)SEQ * DQ, kb, (long)SEQ * DQ,
                                         nullptr, mask, (long)SEQ * SEQ,
                                         pb, (long)SEQ * SEQ, SEQ, DQ, 0.03125f, 1);

    // softmax over rows
    softmax_kernel<<<BATCH * SEQ, 256>>>(pb);

    // out = P @ V : per batch M = SEQ, N = DV, K = SEQ
    dim3 ga(DV / 128, SEQ / 128, BATCH);
    gemm_nn_kernel<<<ga, blk, SMEM_NN>>>(pb, (long)SEQ * SEQ, vb, (long)SEQ * DV,
                                         out, (long)SEQ * DV, DV, SEQ);
}

// round 8
// speedup vs baseline: 1.0178x; 1.0178x over previous
#include <cuda_runtime.h>
#include <cstdint>

#define BATCH 4
#define SEQ   2048
#define DIN   1024
#define DQ    1024
#define DV    1024

// Scratch (allocation-free rule: __device__ globals)
__device__ float g_q[(size_t)BATCH * SEQ * DQ];
__device__ float g_k[(size_t)BATCH * SEQ * DQ];
__device__ float g_v[(size_t)BATCH * SEQ * DV];
__device__ float g_p[(size_t)BATCH * SEQ * SEQ];
// rounded-input scratch: 3 activations (8.4M ea) + 3 weights (1M ea)
__device__ float g_r[(size_t)3 * BATCH * SEQ * DIN + 3 * (size_t)DQ * DIN];

#define RQ_OFF  ((size_t)0)
#define RK_OFF  ((size_t)BATCH * SEQ * DIN)            // 8388608
#define RV_OFF  ((size_t)2 * BATCH * SEQ * DIN)        // 16777216
#define RWQ_OFF ((size_t)3 * BATCH * SEQ * DIN)        // 25165824
#define RWK_OFF (RWQ_OFF + (size_t)DQ * DIN)           // 26214400
#define RWV_OFF (RWK_OFF + (size_t)DQ * DIN)           // 27262976

__device__ __forceinline__ uint32_t f2tf32(float x) {
    uint32_t r;
    asm("cvt.rna.tf32.f32 %0, %1;" : "=r"(r) : "f"(x));
    return r;
}

__device__ __forceinline__ void mma8(float* c, const uint32_t* a, const uint32_t* b) {
    asm volatile(
        "mma.sync.aligned.m16n8k8.row.col.f32.tf32.tf32.f32 "
        "{%0,%1,%2,%3}, {%4,%5,%6,%7}, {%8,%9}, {%0,%1,%2,%3};"
        : "+f"(c[0]), "+f"(c[1]), "+f"(c[2]), "+f"(c[3])
        : "r"(a[0]), "r"(a[1]), "r"(a[2]), "r"(a[3]), "r"(b[0]), "r"(b[1]));
}

__device__ __forceinline__ void cpa16(float* s, const float* g) {
    unsigned sa = (unsigned)__cvta_generic_to_shared(s);
    asm volatile("cp.async.cg.shared.global [%0], [%1], 16;" :: "r"(sa), "l"(g));
}
__device__ __forceinline__ void cpa_commit() { asm volatile("cp.async.commit_group;"); }
__device__ __forceinline__ void cpa_wait0()  { asm volatile("cp.async.wait_group 0;"); }
__device__ __forceinline__ void cpa_wait1()  { asm volatile("cp.async.wait_group 1;"); }

__device__ __forceinline__ uint32_t ldsu(const float* p) {
    return __float_as_uint(*p);   // operands pre-rounded to tf32 grid: no cvt needed
}

// ===========================================================================
// RNA-round fp32 -> tf32-exact fp32 (one-time pre-pass; makes all GEMM inner
// loops cvt-free while keeping numerics identical to cvt-per-fragment)
// ===========================================================================
__global__ void round_tf32_kernel(const float* __restrict__ in, float* __restrict__ out)
{
    long i = ((long)blockIdx.x * 256 + threadIdx.x) * 4;
    float4 v = *(const float4*)(in + i);
    v.x = __uint_as_float(f2tf32(v.x));
    v.y = __uint_as_float(f2tf32(v.y));
    v.z = __uint_as_float(f2tf32(v.z));
    v.w = __uint_as_float(f2tf32(v.w));
    *(float4*)(out + i) = v;
}

// ---------------------------------------------------------------------------
// GEMM NT: C[m][n] = sum_k A[m][k] * B[n][k]  (+ epilogue). Inputs must be
// tf32-grid-exact. epi 0: C = rna(acc + bias[n]) ; epi 1: masked scale.
// Tiles: BM=BN=128, BK=32. 256 threads, 8 warps (2x4), warp tile 64x32.
// ---------------------------------------------------------------------------
__global__ __launch_bounds__(256, 2)
void gemm_nt_kernel(const float* __restrict__ A, long sAz,
                    const float* __restrict__ B, long sBz,
                    const float* __restrict__ bias,
                    const int* __restrict__ mask, long sMz,
                    float* __restrict__ C, long sCz,
                    int N, int K, float scale, int epi)
{
    extern __shared__ float sm[];
    float* sA = sm;              // [2][128][36]
    float* sB = sm + 2 * 128 * 36;

    const int tid  = threadIdx.x;
    const int lane = tid & 31, warp = tid >> 5;
    const int wm = warp >> 2, wn = warp & 3;   // 2 x 4 warp grid
    const int gq = lane >> 2, tg = lane & 3;

    const float* Ab = A + (long)blockIdx.z * sAz + (long)blockIdx.y * 128 * K;
    const float* Bb = B + (long)blockIdx.z * sBz + (long)blockIdx.x * 128 * K;

    float acc[4][4][4];
#pragma unroll
    for (int i = 0; i < 4; i++)
#pragma unroll
        for (int j = 0; j < 4; j++)
#pragma unroll
            for (int l = 0; l < 4; l++) acc[i][j][l] = 0.f;

    const int NIT = K >> 5;

    // prologue: stage 0
#pragma unroll
    for (int i = 0; i < 4; i++) {
        int idx = i * 256 + tid;
        int r = idx >> 3, c = (idx & 7) << 2;
        cpa16(&sA[r * 36 + c], Ab + (long)r * K + c);
        cpa16(&sB[r * 36 + c], Bb + (long)r * K + c);
    }
    cpa_commit();

    for (int it = 0; it < NIT; ++it) {
        int s = it & 1;
        if (it + 1 < NIT) {
            int k0 = (it + 1) << 5;
            float* dA = sA + (s ^ 1) * 4608;
            float* dB = sB + (s ^ 1) * 4608;
#pragma unroll
            for (int i = 0; i < 4; i++) {
                int idx = i * 256 + tid;
                int r = idx >> 3, c = (idx & 7) << 2;
                cpa16(&dA[r * 36 + c], Ab + (long)r * K + k0 + c);
                cpa16(&dB[r * 36 + c], Bb + (long)r * K + k0 + c);
            }
            cpa_commit();
            cpa_wait1();
        } else {
            cpa_wait0();
        }
        __syncthreads();

        const float* cA = sA + s * 4608;
        const float* cB = sB + s * 4608;
#pragma unroll
        for (int ks = 0; ks < 4; ++ks) {
            uint32_t af[4][4];
            uint32_t bf[4][2];
#pragma unroll
            for (int mt = 0; mt < 4; ++mt) {
                int r = wm * 64 + mt * 16 + gq;
                int c = ks * 8 + tg;
                af[mt][0] = ldsu(&cA[r * 36 + c]);
                af[mt][1] = ldsu(&cA[(r + 8) * 36 + c]);
                af[mt][2] = ldsu(&cA[r * 36 + c + 4]);
                af[mt][3] = ldsu(&cA[(r + 8) * 36 + c + 4]);
            }
#pragma unroll
            for (int nt = 0; nt < 4; ++nt) {
                int r = wn * 32 + nt * 8 + gq;
                int c = ks * 8 + tg;
                bf[nt][0] = ldsu(&cB[r * 36 + c]);
                bf[nt][1] = ldsu(&cB[r * 36 + c + 4]);
            }
#pragma unroll
            for (int mt = 0; mt < 4; ++mt)
#pragma unroll
                for (int nt = 0; nt < 4; ++nt)
                    mma8(acc[mt][nt], af[mt], bf[nt]);
        }
        __syncthreads();
    }

    // epilogue
    C += (long)blockIdx.z * sCz;
    if (epi == 1) mask += (long)blockIdx.z * sMz;
#pragma unroll
    for (int mt = 0; mt < 4; ++mt) {
        int row = blockIdx.y * 128 + wm * 64 + mt * 16 + gq;
#pragma unroll
        for (int nt = 0; nt < 4; ++nt) {
            int col = blockIdx.x * 128 + wn * 32 + nt * 8 + tg * 2;
            float* a = acc[mt][nt];
            long r0 = (long)row * N, r1 = (long)(row + 8) * N;
            if (epi == 0) {
                float b0 = bias[col], b1 = bias[col + 1];
                // round so downstream GEMMs can skip cvt (numerically == R3)
                C[r0 + col]     = __uint_as_float(f2tf32(a[0] + b0));
                C[r0 + col + 1] = __uint_as_float(f2tf32(a[1] + b1));
                C[r1 + col]     = __uint_as_float(f2tf32(a[2] + b0));
                C[r1 + col + 1] = __uint_as_float(f2tf32(a[3] + b1));
            } else {
                C[r0 + col]     = mask[r0 + col]     ? -1.0e9f : a[0] * scale;
                C[r0 + col + 1] = mask[r0 + col + 1] ? -1.0e9f : a[1] * scale;
                C[r1 + col]     = mask[r1 + col]     ? -1.0e9f : a[2] * scale;
                C[r1 + col + 1] = mask[r1 + col + 1] ? -1.0e9f : a[3] * scale;
            }
        }
    }
}

// ---------------------------------------------------------------------------
// GEMM NN: C[m][n] = sum_k A[m][k] * B[k][n]   (out = P @ V). Inputs
// pre-rounded (P by softmax, V by projection epilogue) -> cvt-free.
// ---------------------------------------------------------------------------
__global__ __launch_bounds__(256, 2)
void gemm_nn_kernel(const float* __restrict__ A, long sAz,
                    const float* __restrict__ B, long sBz,
                    float* __restrict__ C, long sCz,
                    int N, int K)
{
    extern __shared__ float sm[];
    float* sA = sm;            // [2][128][36]
    float* sB = sm + 9216;     // [2][32][132]

    const int tid  = threadIdx.x;
    const int lane = tid & 31, warp = tid >> 5;
    const int wm = warp >> 2, wn = warp & 3;
    const int gq = lane >> 2, tg = lane & 3;

    const float* Ab = A + (long)blockIdx.z * sAz + (long)blockIdx.y * 128 * K;
    const float* Bb = B + (long)blockIdx.z * sBz + (long)blockIdx.x * 128;

    float acc[4][4][4];
#pragma unroll
    for (int i = 0; i < 4; i++)
#pragma unroll
        for (int j = 0; j < 4; j++)
#pragma unroll
            for (int l = 0; l < 4; l++) acc[i][j][l] = 0.f;

    const int NIT = K >> 5;

#pragma unroll
    for (int i = 0; i < 4; i++) {
        int idx = i * 256 + tid;
        int ra = idx >> 3, ca = (idx & 7) << 2;
        cpa16(&sA[ra * 36 + ca], Ab + (long)ra * K + ca);
        int rb = idx >> 5, cb = (idx & 31) << 2;
        cpa16(&sB[rb * 132 + cb], Bb + (long)rb * N + cb);
    }
    cpa_commit();

    for (int it = 0; it < NIT; ++it) {
        int s = it & 1;
        if (it + 1 < NIT) {
            int k0 = (it + 1) << 5;
            float* dA = sA + (s ^ 1) * 4608;
            float* dB = sB + (s ^ 1) * 4224;
#pragma unroll
            for (int i = 0; i < 4; i++) {
                int idx = i * 256 + tid;
                int ra = idx >> 3, ca = (idx & 7) << 2;
                cpa16(&dA[ra * 36 + ca], Ab + (long)ra * K + k0 + ca);
                int rb = idx >> 5, cb = (idx & 31) << 2;
                cpa16(&dB[rb * 132 + cb], Bb + (long)(k0 + rb) * N + cb);
            }
            cpa_commit();
            cpa_wait1();
        } else {
            cpa_wait0();
        }
        __syncthreads();

        const float* cA = sA + s * 4608;
        const float* cB = sB + s * 4224;
#pragma unroll
        for (int ks = 0; ks < 4; ++ks) {
            uint32_t af[4][4];
            uint32_t bf[4][2];
#pragma unroll
            for (int mt = 0; mt < 4; ++mt) {
                int r = wm * 64 + mt * 16 + gq;
                int c = ks * 8 + tg;
                af[mt][0] = ldsu(&cA[r * 36 + c]);
                af[mt][1] = ldsu(&cA[(r + 8) * 36 + c]);
                af[mt][2] = ldsu(&cA[r * 36 + c + 4]);
                af[mt][3] = ldsu(&cA[(r + 8) * 36 + c + 4]);
            }
#pragma unroll
            for (int nt = 0; nt < 4; ++nt) {
                int n = wn * 32 + nt * 8 + gq;
                int k = ks * 8 + tg;
                bf[nt][0] = ldsu(&cB[k * 132 + n]);
                bf[nt][1] = ldsu(&cB[(k + 4) * 132 + n]);
            }
#pragma unroll
            for (int mt = 0; mt < 4; ++mt)
#pragma unroll
                for (int nt = 0; nt < 4; ++nt)
                    mma8(acc[mt][nt], af[mt], bf[nt]);
        }
        __syncthreads();
    }

    C += (long)blockIdx.z * sCz;
#pragma unroll
    for (int mt = 0; mt < 4; ++mt) {
        int row = blockIdx.y * 128 + wm * 64 + mt * 16 + gq;
#pragma unroll
        for (int nt = 0; nt < 4; ++nt) {
            int col = blockIdx.x * 128 + wn * 32 + nt * 8 + tg * 2;
            float* a = acc[mt][nt];
            long r0 = (long)row * N, r1 = (long)(row + 8) * N;
            C[r0 + col]     = a[0];
            C[r0 + col + 1] = a[1];
            C[r1 + col]     = a[2];
            C[r1 + col + 1] = a[3];
        }
    }
}

// ---------------------------------------------------------------------------
// Row softmax over P; writes tf32-rounded probabilities (== R3's PV-side cvt).
// ---------------------------------------------------------------------------
__global__ void softmax_kernel(float* __restrict__ P)
{
    float* p = P + (long)blockIdx.x * SEQ;
    const int tid = threadIdx.x;
    __shared__ float red[8];

    float v[8];
    float mx = -3.4e38f;
#pragma unroll
    for (int i = 0; i < 8; i++) {
        v[i] = p[tid + (i << 8)];
        mx = fmaxf(mx, v[i]);
    }
#pragma unroll
    for (int o = 16; o > 0; o >>= 1) mx = fmaxf(mx, __shfl_xor_sync(0xffffffffu, mx, o));
    if ((tid & 31) == 0) red[tid >> 5] = mx;
    __syncthreads();
    mx = red[0];
#pragma unroll
    for (int i = 1; i < 8; i++) mx = fmaxf(mx, red[i]);

    float sum = 0.f;
#pragma unroll
    for (int i = 0; i < 8; i++) {
        v[i] = expf(v[i] - mx);
        sum += v[i];
    }
#pragma unroll
    for (int o = 16; o > 0; o >>= 1) sum += __shfl_xor_sync(0xffffffffu, sum, o);
    __syncthreads();
    if ((tid & 31) == 0) red[tid >> 5] = sum;
    __syncthreads();
    float tot = 0.f;
#pragma unroll
    for (int i = 0; i < 8; i++) tot += red[i];
    float inv = 1.0f / tot;
#pragma unroll
    for (int i = 0; i < 8; i++)
        p[tid + (i << 8)] = __uint_as_float(f2tf32(v[i] * inv));
}

// ---------------------------------------------------------------------------
extern "C" void kernel_launch(void* const* d_in, const int* in_sizes, int n_in,
                              void* d_out, int out_size)
{
    const float* query = (const float*)d_in[0];
    const float* key   = (const float*)d_in[1];
    const float* value = (const float*)d_in[2];
    const int*   mask  = (const int*)d_in[3];     // bool stored as int32
    const float* Wq = (const float*)d_in[4];
    const float* bq = (const float*)d_in[5];
    const float* Wk = (const float*)d_in[6];
    const float* bk = (const float*)d_in[7];
    const float* Wv = (const float*)d_in[8];
    const float* bv = (const float*)d_in[9];
    float* out = (float*)d_out;

    float *qb, *kb, *vb, *pb, *rb;
    cudaGetSymbolAddress((void**)&qb, g_q);
    cudaGetSymbolAddress((void**)&kb, g_k);
    cudaGetSymbolAddress((void**)&vb, g_v);
    cudaGetSymbolAddress((void**)&pb, g_p);
    cudaGetSymbolAddress((void**)&rb, g_r);

    const int SMEM_NT = (2 * 128 * 36 * 2) * 4;              // 73728 B
    const int SMEM_NN = (2 * 128 * 36 + 2 * 32 * 132) * 4;   // 70656 B
    cudaFuncSetAttribute(gemm_nt_kernel, cudaFuncAttributeMaxDynamicSharedMemorySize, SMEM_NT);
    cudaFuncSetAttribute(gemm_nn_kernel, cudaFuncAttributeMaxDynamicSharedMemorySize, SMEM_NN);

    // one-time RNA rounding of all projection-GEMM inputs (scratch in g_r)
    const long NACT = (long)BATCH * SEQ * DIN;   // 8388608
    round_tf32_kernel<<<NACT / 1024, 256>>>(query, rb + RQ_OFF);
    round_tf32_kernel<<<NACT / 1024, 256>>>(key,   rb + RK_OFF);
    round_tf32_kernel<<<NACT / 1024, 256>>>(value, rb + RV_OFF);
    round_tf32_kernel<<<(DQ * DIN) / 1024, 256>>>(Wq, rb + RWQ_OFF);
    round_tf32_kernel<<<(DQ * DIN) / 1024, 256>>>(Wk, rb + RWK_OFF);
    round_tf32_kernel<<<(DV * DIN) / 1024, 256>>>(Wv, rb + RWV_OFF);

    dim3 blk(256);

    // QKV projections: M = B*S = 8192, N = 1024, K = 1024
    dim3 gp(DQ / 128, (BATCH * SEQ) / 128, 1);
    gemm_nt_kernel<<<gp, blk, SMEM_NT>>>(rb + RQ_OFF, 0, rb + RWQ_OFF, 0, bq,
                                         nullptr, 0, qb, 0, DQ, DIN, 0.f, 0);
    gemm_nt_kernel<<<gp, blk, SMEM_NT>>>(rb + RK_OFF, 0, rb + RWK_OFF, 0, bk,
                                         nullptr, 0, kb, 0, DQ, DIN, 0.f, 0);
    gemm_nt_kernel<<<gp, blk, SMEM_NT>>>(rb + RV_OFF, 0, rb + RWV_OFF, 0, bv,
                                         nullptr, 0, vb, 0, DV, DIN, 0.f, 0);

    // scores: per batch M = N = SEQ, K = DQ, scale = 1/sqrt(1024)
    dim3 gs(SEQ / 128, SEQ / 128, BATCH);
    gemm_nt_kernel<<<gs, blk, SMEM_NT>>>(qb, (long)SEQ * DQ, kb, (long)SEQ * DQ,
                                         nullptr, mask, (long)SEQ * SEQ,
                                         pb, (long)SEQ * SEQ, SEQ, DQ, 0.03125f, 1);

    // softmax over rows
    softmax_kernel<<<BATCH * SEQ, 256>>>(pb);

    // out = P @ V : per batch M = SEQ, N = DV, K = SEQ
    dim3 ga(DV / 128, SEQ / 128, BATCH);
    gemm_nn_kernel<<<ga, blk, SMEM_NN>>>(pb, (long)SEQ * SEQ, vb, (long)SEQ * DV,
                                         out, (long)SEQ * DV, DV, SEQ);
}